// round 16
// baseline (speedup 1.0000x reference)
#include <cuda_runtime.h>
#include <cuda_fp16.h>
#include <mma.h>
#include <cstdint>

using namespace nvcuda;

#define BATCH 32768
#define DIN   768
#define DHID  2048
#define TOPK  32

// -------- scratch (no cudaMalloc allowed) --------
__device__ __align__(16) __half g_Wt[(size_t)DHID * DIN];  // W_dec^T fp16 [2048][768]
__device__ int   g_tidx[(size_t)BATCH * TOPK];
__device__ float g_tval[(size_t)BATCH * TOPK];
__device__ __align__(16) __half g_Ah[(size_t)BATCH * DIN];  // x rounded to fp16
__device__ __align__(16) __half g_Bh[(size_t)DHID * DIN];   // W_enc rounded to fp16

// ============================================================
// f32 -> fp16 round (used for both x and W_enc)
// ============================================================
__global__ __launch_bounds__(256)
void round_x_kernel(const float* __restrict__ src, __half* __restrict__ dst)
{
    int i = blockIdx.x * 256 + threadIdx.x;
    float2 v = ((const float2*)src)[i];
    ((__half2*)dst)[i] = __floats2half2_rn(v.x, v.y);
}

// ============================================================
// W_dec [768][2048] -> g_Wt [2048][768] (fp16)
// ============================================================
__global__ void transpose_kernel(const float* __restrict__ W)
{
    __shared__ float tile[32][33];
    int bx = blockIdx.x * 32, by = blockIdx.y * 32;
    int tx = threadIdx.x, ty = threadIdx.y;
#pragma unroll
    for (int i = 0; i < 32; i += 8)
        tile[ty + i][tx] = W[(size_t)(by + ty + i) * DHID + bx + tx];
    __syncthreads();
#pragma unroll
    for (int i = 0; i < 32; i += 8)
        g_Wt[(size_t)(bx + ty + i) * DIN + by + tx] = __float2half_rn(tile[tx][ty + i]);
}

// ============================================================
// Encoder GEMM, pure fp16, cp.async 2-stage, 4 CTAs/SM.
// Block 128Mx64N, 4 warps (wm 2 x wn 2), warp tile 64x32, BK=32.
// 4 independent barrier domains per SM hide per-tile syncs.
// ============================================================
#define BK      32
#define HS      40                      // halves per row (32 + 8 pad)
#define PART_A  (128 * HS)              // 5120 halves
#define PART_B  (64 * HS)               // 2560 halves
#define STG_H   (PART_A + PART_B)       // 7680 halves / stage
#define NKT     (DIN / BK)              // 24
#define GEMM_SMEM (2 * STG_H * sizeof(__half))   // 30720 B

__device__ __forceinline__ void cp16(__half* dst, const __half* src)
{
    unsigned d = (unsigned)__cvta_generic_to_shared(dst);
    asm volatile("cp.async.cg.shared.global [%0], [%1], 16;\n" :: "r"(d), "l"(src));
}

__global__ __launch_bounds__(128, 4)
void gemm_fp16(const float* __restrict__ bias, float* __restrict__ C)
{
    extern __shared__ __half smh[];   // 2 stages

    int tid  = threadIdx.x;
    int warp = tid >> 5;
    int wm   = warp & 1;        // 0..1 : 64-row M slab
    int wn   = warp >> 1;       // 0..1 : 32-col N slab
    int m0 = blockIdx.y * 128;
    int n0 = blockIdx.x * 64;

    using FragA = wmma::fragment<wmma::matrix_a, 16, 16, 16, __half, wmma::row_major>;
    using FragB = wmma::fragment<wmma::matrix_b, 16, 16, 16, __half, wmma::col_major>;
    using FragC = wmma::fragment<wmma::accumulator, 16, 16, 16, float>;

    // ---- bias init via smem f32 broadcast tile (reuses stage region) ----
    float* bsm = (float*)smh;
    for (int i = tid; i < 16 * 64; i += 128)
        bsm[i] = bias[n0 + (i & 63)];
    __syncthreads();

    FragC acc[4][2];
#pragma unroll
    for (int i = 0; i < 4; i++)
#pragma unroll
        for (int j = 0; j < 2; j++)
            wmma::load_matrix_sync(acc[i][j], &bsm[wn * 32 + j * 16], 64, wmma::mem_row_major);
    __syncthreads();

    auto load_tile = [&](int buf, int kt) {
        __half* s = smh + buf * STG_H;
        int k0 = kt * BK;
        // A: 128 rows x 32 halves = 512 cp16 -> 4 per thread
#pragma unroll
        for (int p = 0; p < 4; p++) {
            int f  = tid + p * 128;      // 0..511
            int r  = f >> 2;             // 0..127
            int ch = (f & 3) * 8;
            cp16(&s[r * HS + ch], &g_Ah[(size_t)(m0 + r) * DIN + k0 + ch]);
        }
        // B: 64 rows x 32 halves = 256 cp16 -> 2 per thread
#pragma unroll
        for (int p = 0; p < 2; p++) {
            int f  = tid + p * 128;      // 0..255
            int r  = f >> 2;             // 0..63
            int ch = (f & 3) * 8;
            cp16(&s[PART_A + r * HS + ch], &g_Bh[(size_t)(n0 + r) * DIN + k0 + ch]);
        }
        asm volatile("cp.async.commit_group;\n" ::);
    };

    load_tile(0, 0);

    for (int t = 0; t < NKT; t++) {
        if (t + 1 < NKT) load_tile((t + 1) & 1, t + 1);
        else             asm volatile("cp.async.commit_group;\n" ::);

        asm volatile("cp.async.wait_group 1;\n" ::);
        __syncthreads();

        __half* s  = smh + (t & 1) * STG_H;
        __half* Ah = s;
        __half* Bh = s + PART_A;

#pragma unroll
        for (int ks = 0; ks < BK; ks += 16) {
            FragB bh[2];
#pragma unroll
            for (int j = 0; j < 2; j++)
                wmma::load_matrix_sync(bh[j], &Bh[(wn * 32 + j * 16) * HS + ks], HS);
#pragma unroll
            for (int i = 0; i < 4; i++) {
                FragA ah;
                wmma::load_matrix_sync(ah, &Ah[(wm * 64 + i * 16) * HS + ks], HS);
#pragma unroll
                for (int j = 0; j < 2; j++)
                    wmma::mma_sync(acc[i][j], ah, bh[j], acc[i][j]);
            }
        }
        __syncthreads();
    }

#pragma unroll
    for (int i = 0; i < 4; i++)
#pragma unroll
        for (int j = 0; j < 2; j++) {
            float* cp = &C[(size_t)(m0 + wm * 64 + i * 16) * DHID + n0 + wn * 32 + j * 16];
            wmma::store_matrix_sync(cp, acc[i][j], DHID, wmma::mem_row_major);
        }
}

// ============================================================
// Top-K v3.1 (R15 best): candidate-compressed bisection
// + exact fp64 re-rank of the ambiguous boundary.
// Element layout: val[4g+c] = column g*128 + lane*4 + c.
// ============================================================
#define AMBIG_W 1.5e-3f
#define MAXCAND 16

__device__ __forceinline__ unsigned fmono(float f)
{
    unsigned u = __float_as_uint(f);
    return (u & 0x80000000u) ? ~u : (u | 0x80000000u);
}
__device__ __forceinline__ float key_decode(unsigned k)
{
    return (k >= 0x80000000u) ? __uint_as_float(k ^ 0x80000000u)
                              : __uint_as_float(~k);
}

__global__ __launch_bounds__(256, 2)
void topk_kernel(const float* __restrict__ hpre, float* __restrict__ hsp,
                 const float* __restrict__ x, const float* __restrict__ Wenc)
{
    const unsigned FULL = 0xFFFFFFFFu;
    int lane = threadIdx.x & 31;
    int warp = threadIdx.x >> 5;
    int row  = blockIdx.x * 8 + warp;
    const float4* p4 = (const float4*)(hpre + (size_t)row * DHID);
    unsigned lmask = (1u << lane) - 1u;

    __shared__ float  s_cv[8][128];
    __shared__ int    s_cidx[8][MAXCAND];
    __shared__ double s_cval[8][MAXCAND];
    __shared__ int    s_csel[8][MAXCAND];
    __shared__ unsigned s_chosen[8];

    float val[64];
    float vmax = -3.0e38f;
#pragma unroll
    for (int g = 0; g < 16; g++) {
        float4 v = p4[g * 32 + lane];
        val[4*g+0] = v.x; val[4*g+1] = v.y; val[4*g+2] = v.z; val[4*g+3] = v.w;
        vmax = fmaxf(vmax, fmaxf(fmaxf(v.x, v.y), fmaxf(v.z, v.w)));
    }

    unsigned lo = __reduce_min_sync(FULL, fmono(vmax));
    unsigned hi = __reduce_max_sync(FULL, fmono(vmax));
    float loF = key_decode(lo);

    int c_lo;
    {
        int c = 0;
#pragma unroll
        for (int j = 0; j < 64; j++) c += (val[j] >= loF) ? 1 : 0;
        c_lo = __reduce_add_sync(FULL, c);
    }
#pragma unroll 1
    for (int it = 0; it < 32 && c_lo > 128 && lo < hi; ++it) {
        unsigned span = hi - lo;
        unsigned mid = lo + (span >> 1) + (span & 1u);
        float mf = key_decode(mid);
        int c = 0;
#pragma unroll
        for (int j = 0; j < 64; j++) c += (val[j] >= mf) ? 1 : 0;
        c = __reduce_add_sync(FULL, c);
        if (c >= TOPK) { lo = mid; loF = mf; c_lo = c; }
        else            hi = mid - 1;
    }

    int cnt = 0;
#pragma unroll
    for (int j = 0; j < 64; j++) cnt += (val[j] >= loF) ? 1 : 0;
    int off = cnt;
#pragma unroll
    for (int d = 1; d < 32; d <<= 1) {
        int n = __shfl_up_sync(FULL, off, d);
        if (lane >= d) off += n;
    }
    int ncand = __shfl_sync(FULL, off, 31);
    off -= cnt;
    {
        int o = off;
#pragma unroll
        for (int j = 0; j < 64; j++) {
            if (val[j] >= loF) {
                if (o < 128) s_cv[warp][o] = val[j];
                o++;
            }
        }
    }
    if (ncand > 128) ncand = 128;
    __syncwarp();

    float cv[4];
#pragma unroll
    for (int r = 0; r < 4; r++) {
        int pos = lane + r * 32;
        cv[r] = (pos < ncand) ? s_cv[warp][pos] : -3.0e38f;
    }

#pragma unroll 1
    for (int it = 0; it < 32; ++it) {
        if (lo >= hi) break;
        unsigned span = hi - lo;
        unsigned mid = lo + (span >> 1) + (span & 1u);
        float mf = key_decode(mid);
        int c = 0;
#pragma unroll
        for (int r = 0; r < 4; r++)
            c += __popc(__ballot_sync(FULL, cv[r] >= mf));
        if (c >= TOPK) lo = mid; else hi = mid - 1;
    }
    float Tf = key_decode(lo);

    int cg = 0;
#pragma unroll
    for (int r = 0; r < 4; r++)
        cg += __popc(__ballot_sync(FULL, cv[r] > Tf));
    int rem = TOPK - cg;

    unsigned long long selmask = 0ull, tiemask = 0ull;
    float vin_l = 3.0e38f, vout_l = -3.0e38f;
#pragma unroll
    for (int j = 0; j < 64; j++) {
        float v = val[j];
        if (v > Tf)       { selmask |= 1ull << j; vin_l = fminf(vin_l, v); }
        else if (v == Tf) { tiemask |= 1ull << j; }
        else              { vout_l = fmaxf(vout_l, v); }
    }
    int tcnt = __popcll(tiemask);
    int toff = tcnt;
#pragma unroll
    for (int d = 1; d < 32; d <<= 1) {
        int n = __shfl_up_sync(FULL, toff, d);
        if (lane >= d) toff += n;
    }
    toff -= tcnt;
    {
        int r = toff;
#pragma unroll
        for (int j = 0; j < 64; j++) {
            if ((tiemask >> j) & 1ull) {
                if (r < rem) { selmask |= 1ull << j; vin_l = fminf(vin_l, val[j]); }
                else         { vout_l = fmaxf(vout_l, val[j]); }
                r++;
            }
        }
    }

    unsigned vi = __reduce_min_sync(FULL, fmono(vin_l));
    unsigned vo = __reduce_max_sync(FULL, fmono(vout_l));
    float vin  = key_decode(vi);
    float vout = key_decode(vo);

    if (vin - vout < AMBIG_W) {
        float wlo = vout - AMBIG_W;
        float whi = vin + AMBIG_W;
        int ncw = 0;
#pragma unroll 1
        for (int j = 0; j < 64; j++) {
            float v = val[j];
            bool isc = (v >= wlo) && (v <= whi);
            unsigned bal = __ballot_sync(FULL, isc);
            if (isc) {
                int pos = ncw + __popc(bal & lmask);
                if (pos < MAXCAND) {
                    s_cidx[warp][pos] = (j >> 2) * 128 + lane * 4 + (j & 3);
                    s_csel[warp][pos] = (int)((selmask >> j) & 1ull);
                }
            }
            ncw += __popc(bal);
        }
        if (ncw > MAXCAND) ncw = MAXCAND;
        __syncwarp();

        const float* xr = x + (size_t)row * DIN;
        for (int c = 0; c < ncw; c++) {
            const float* wr = Wenc + (size_t)s_cidx[warp][c] * DIN;
            double s = 0.0;
#pragma unroll
            for (int t = 0; t < DIN / 32; t++) {
                int kk = lane + t * 32;
                s += (double)xr[kk] * (double)wr[kk];
            }
#pragma unroll
            for (int o2 = 16; o2 > 0; o2 >>= 1)
                s += __shfl_down_sync(FULL, s, o2);
            if (lane == 0) s_cval[warp][c] = s;
            __syncwarp();
        }

        if (lane == 0) {
            int nkeep = 0;
            for (int c = 0; c < ncw; c++) nkeep += s_csel[warp][c];
            unsigned chosen = 0;
            for (int s = 0; s < nkeep; s++) {
                int best = -1;
                for (int c = 0; c < ncw; c++) {
                    if (chosen & (1u << c)) continue;
                    if (best < 0 ||
                        s_cval[warp][c] > s_cval[warp][best] ||
                        (s_cval[warp][c] == s_cval[warp][best] &&
                         s_cidx[warp][c] < s_cidx[warp][best]))
                        best = c;
                }
                chosen |= (1u << best);
            }
            s_chosen[warp] = chosen;
        }
        __syncwarp();
        unsigned chosen = s_chosen[warp];

        for (int c = 0; c < ncw; c++) {
            int fi = s_cidx[warp][c];
            if (((fi >> 2) & 31) == lane) {
                int j = ((fi >> 7) << 2) | (fi & 3);
                if (chosen & (1u << c)) selmask |=  (1ull << j);
                else                    selmask &= ~(1ull << j);
            }
        }
        __syncwarp();
    }

    float4* orow4 = (float4*)(hsp + (size_t)row * DHID);
#pragma unroll
    for (int g = 0; g < 16; g++) {
        float4 o;
        o.x = ((selmask >> (4*g+0)) & 1ull) ? fmaxf(val[4*g+0], 0.0f) : 0.0f;
        o.y = ((selmask >> (4*g+1)) & 1ull) ? fmaxf(val[4*g+1], 0.0f) : 0.0f;
        o.z = ((selmask >> (4*g+2)) & 1ull) ? fmaxf(val[4*g+2], 0.0f) : 0.0f;
        o.w = ((selmask >> (4*g+3)) & 1ull) ? fmaxf(val[4*g+3], 0.0f) : 0.0f;
        orow4[g * 32 + lane] = o;
    }

    int scnt = __popcll(selmask);
    int soff = scnt;
#pragma unroll
    for (int d = 1; d < 32; d <<= 1) {
        int n = __shfl_up_sync(FULL, soff, d);
        if (lane >= d) soff += n;
    }
    int nsel_tot = __shfl_sync(FULL, soff, 31);
    soff -= scnt;
    {
        int so = soff;
#pragma unroll
        for (int j = 0; j < 64; j++) {
            if ((selmask >> j) & 1ull) {
                if (so < TOPK) {
                    g_tidx[(size_t)row * TOPK + so] = (j >> 2) * 128 + lane * 4 + (j & 3);
                    g_tval[(size_t)row * TOPK + so] = fmaxf(val[j], 0.0f);
                }
                so++;
            }
        }
    }
    if (nsel_tot < TOPK && lane == 0) {
        for (int s = nsel_tot; s < TOPK; s++) {
            g_tidx[(size_t)row * TOPK + s] = 0;
            g_tval[(size_t)row * TOPK + s] = 0.0f;
        }
    }
}

// ============================================================
// Sparse decoder: recon[row,:] = b_dec + sum_k val_k * Wt[idx_k,:]
// Wt in fp16 (math fp32).
// ============================================================
__global__ __launch_bounds__(192)
void decode_kernel(const float* __restrict__ bdec, float* __restrict__ recon)
{
    int row = blockIdx.x;
    int t = threadIdx.x;
    __shared__ float sval[TOPK];
    __shared__ int   sidx[TOPK];
    if (t < TOPK) {
        sval[t] = g_tval[(size_t)row * TOPK + t];
        sidx[t] = g_tidx[(size_t)row * TOPK + t];
    }
    __syncthreads();

    float4 acc = *(const float4*)&bdec[t * 4];
#pragma unroll 8
    for (int k = 0; k < TOPK; k++) {
        float v = sval[k];
        const __half* wr = g_Wt + (size_t)sidx[k] * DIN;
        uint2 u = ((const uint2*)wr)[t];
        __half2 h01 = *(__half2*)&u.x;
        __half2 h23 = *(__half2*)&u.y;
        float2 f01 = __half22float2(h01);
        float2 f23 = __half22float2(h23);
        acc.x += v * f01.x; acc.y += v * f01.y;
        acc.z += v * f23.x; acc.w += v * f23.y;
    }
    *(float4*)&recon[(size_t)row * DIN + t * 4] = acc;
}

// ============================================================
extern "C" void kernel_launch(void* const* d_in, const int* in_sizes, int n_in,
                              void* d_out, int out_size)
{
    const float* x     = (const float*)d_in[0];
    const float* W_enc = (const float*)d_in[1];
    const float* b_enc = (const float*)d_in[2];
    const float* W_dec = (const float*)d_in[3];
    const float* b_dec = (const float*)d_in[4];

    float* out   = (float*)d_out;
    float* recon = out;                                 // [B, 768]
    float* hsp   = out + (size_t)BATCH * DIN;           // [B, 2048]
    float* hpre  = hsp + (size_t)BATCH * DHID;          // [B, 2048]

    __half *ah, *bh;
    cudaGetSymbolAddress((void**)&ah, g_Ah);
    cudaGetSymbolAddress((void**)&bh, g_Bh);

    cudaFuncSetAttribute(gemm_fp16, cudaFuncAttributeMaxDynamicSharedMemorySize,
                         (int)GEMM_SMEM);

    round_x_kernel<<<(BATCH * DIN / 2) / 256, 256>>>(x, ah);
    round_x_kernel<<<(DHID * DIN / 2) / 256, 256>>>(W_enc, bh);
    transpose_kernel<<<dim3(DHID / 32, DIN / 32), dim3(32, 8)>>>(W_dec);
    gemm_fp16<<<dim3(DHID / 64, BATCH / 128), 128, GEMM_SMEM>>>(b_enc, hpre);
    topk_kernel<<<BATCH / 8, 256>>>(hpre, hsp, x, W_enc);
    decode_kernel<<<BATCH, 192>>>(b_dec, recon);
}

// round 17
// speedup vs baseline: 1.2827x; 1.2827x over previous
#include <cuda_runtime.h>
#include <cuda_fp16.h>
#include <mma.h>
#include <cstdint>

using namespace nvcuda;

#define BATCH 32768
#define DIN   768
#define DHID  2048
#define TOPK  32

// -------- scratch (no cudaMalloc allowed) --------
__device__ __align__(16) __half g_Wt[(size_t)DHID * DIN];  // W_dec^T fp16 [2048][768]
__device__ int   g_tidx[(size_t)BATCH * TOPK];
__device__ float g_tval[(size_t)BATCH * TOPK];
__device__ __align__(16) __half g_Ah[(size_t)BATCH * DIN];  // x rounded to fp16
__device__ __align__(16) __half g_Bh[(size_t)DHID * DIN];   // W_enc rounded to fp16

// ============================================================
// f32 -> fp16 round (used for both x and W_enc)
// ============================================================
__global__ __launch_bounds__(256)
void round_x_kernel(const float* __restrict__ src, __half* __restrict__ dst)
{
    int i = blockIdx.x * 256 + threadIdx.x;
    float2 v = ((const float2*)src)[i];
    ((__half2*)dst)[i] = __floats2half2_rn(v.x, v.y);
}

// ============================================================
// W_dec [768][2048] -> g_Wt [2048][768] (fp16)
// ============================================================
__global__ void transpose_kernel(const float* __restrict__ W)
{
    __shared__ float tile[32][33];
    int bx = blockIdx.x * 32, by = blockIdx.y * 32;
    int tx = threadIdx.x, ty = threadIdx.y;
#pragma unroll
    for (int i = 0; i < 32; i += 8)
        tile[ty + i][tx] = W[(size_t)(by + ty + i) * DHID + bx + tx];
    __syncthreads();
#pragma unroll
    for (int i = 0; i < 32; i += 8)
        g_Wt[(size_t)(bx + ty + i) * DIN + by + tx] = __float2half_rn(tile[tx][ty + i]);
}

// ============================================================
// Encoder GEMM (R15 config, best measured 314us): pure fp16,
// cp.async 3-stage, BK=64, 2 CTAs/SM, block 128x128,
// 8 warps (Wm=2,Wn=4), warp tile 64x32.
// ============================================================
#define BK     64
#define HS     72                       // halves per row (64 + 8 pad, 144B)
#define PART   (128 * HS)               // 9216 halves
#define STG_H  (2 * PART)               // 18432 halves / stage
#define NKT    (DIN / BK)               // 12
#define GEMM_SMEM (3 * STG_H * sizeof(__half))   // 110592 B

__device__ __forceinline__ void cp16(__half* dst, const __half* src)
{
    unsigned d = (unsigned)__cvta_generic_to_shared(dst);
    asm volatile("cp.async.cg.shared.global [%0], [%1], 16;\n" :: "r"(d), "l"(src));
}

__global__ __launch_bounds__(256, 2)
void gemm_fp16(const float* __restrict__ bias, float* __restrict__ C)
{
    extern __shared__ __half smh[];   // 3 stages

    int tid  = threadIdx.x;
    int warp = tid >> 5;
    int wm   = warp & 1;
    int wn   = warp >> 1;
    int m0 = blockIdx.y * 128;
    int n0 = blockIdx.x * 128;

    using FragA = wmma::fragment<wmma::matrix_a, 16, 16, 16, __half, wmma::row_major>;
    using FragB = wmma::fragment<wmma::matrix_b, 16, 16, 16, __half, wmma::col_major>;
    using FragC = wmma::fragment<wmma::accumulator, 16, 16, 16, float>;

    float* bsm = (float*)smh;
    for (int i = tid; i < 16 * 128; i += 256)
        bsm[i] = bias[n0 + (i & 127)];
    __syncthreads();

    FragC acc[4][2];
#pragma unroll
    for (int i = 0; i < 4; i++)
#pragma unroll
        for (int j = 0; j < 2; j++)
            wmma::load_matrix_sync(acc[i][j], &bsm[wn * 32 + j * 16], 128, wmma::mem_row_major);
    __syncthreads();

    auto load_tile = [&](int buf, int kt) {
        __half* s = smh + buf * STG_H;
        int k0 = kt * BK;
#pragma unroll
        for (int p = 0; p < 4; p++) {
            int f  = tid + p * 256;
            int r  = f >> 3;
            int ch = (f & 7) * 8;
            size_t ga = (size_t)(m0 + r) * DIN + k0 + ch;
            size_t gb = (size_t)(n0 + r) * DIN + k0 + ch;
            cp16(&s[0 * PART + r * HS + ch], &g_Ah[ga]);
            cp16(&s[1 * PART + r * HS + ch], &g_Bh[gb]);
        }
        asm volatile("cp.async.commit_group;\n" ::);
    };

    load_tile(0, 0);
    load_tile(1, 1);

    int buf = 0;
    for (int t = 0; t < NKT; t++) {
        asm volatile("cp.async.wait_group 1;\n" ::);
        __syncthreads();

        if (t + 2 < NKT) load_tile((t + 2) % 3, t + 2);
        else             asm volatile("cp.async.commit_group;\n" ::);

        __half* s  = smh + buf * STG_H;
        buf = (buf + 1 == 3) ? 0 : buf + 1;
        __half* Ah = s;
        __half* Bh = s + PART;

#pragma unroll
        for (int ks = 0; ks < BK; ks += 16) {
            FragB bh[2];
#pragma unroll
            for (int j = 0; j < 2; j++)
                wmma::load_matrix_sync(bh[j], &Bh[(wn * 32 + j * 16) * HS + ks], HS);
#pragma unroll
            for (int i = 0; i < 4; i++) {
                FragA ah;
                wmma::load_matrix_sync(ah, &Ah[(wm * 64 + i * 16) * HS + ks], HS);
#pragma unroll
                for (int j = 0; j < 2; j++)
                    wmma::mma_sync(acc[i][j], ah, bh[j], acc[i][j]);
            }
        }
    }

#pragma unroll
    for (int i = 0; i < 4; i++)
#pragma unroll
        for (int j = 0; j < 2; j++) {
            float* cp = &C[(size_t)(m0 + wm * 64 + i * 16) * DHID + n0 + wn * 32 + j * 16];
            wmma::store_matrix_sync(cp, acc[i][j], DHID, wmma::mem_row_major);
        }
}

// ============================================================
// Top-K v4: candidate-compressed bisection with SPARSE BIT
// ITERATION (ffs loops) replacing 64-iter predicated loops.
// + exact fp64 re-rank of the ambiguous boundary.
// Element layout: val[4g+c] = column g*128 + lane*4 + c.
// ============================================================
#define AMBIG_W 1.5e-3f
#define MAXCAND 16

__device__ __forceinline__ unsigned fmono(float f)
{
    unsigned u = __float_as_uint(f);
    return (u & 0x80000000u) ? ~u : (u | 0x80000000u);
}
__device__ __forceinline__ float key_decode(unsigned k)
{
    return (k >= 0x80000000u) ? __uint_as_float(k ^ 0x80000000u)
                              : __uint_as_float(~k);
}

__global__ __launch_bounds__(256, 2)
void topk_kernel(const float* __restrict__ hpre, float* __restrict__ hsp,
                 const float* __restrict__ x, const float* __restrict__ Wenc)
{
    const unsigned FULL = 0xFFFFFFFFu;
    int lane = threadIdx.x & 31;
    int warp = threadIdx.x >> 5;
    int row  = blockIdx.x * 8 + warp;
    const float4* p4 = (const float4*)(hpre + (size_t)row * DHID);

    __shared__ float  s_cv[8][128];
    __shared__ int    s_cidx[8][MAXCAND];
    __shared__ double s_cval[8][MAXCAND];
    __shared__ int    s_csel[8][MAXCAND];
    __shared__ unsigned s_chosen[8];

    float val[64];
    float vmax = -3.0e38f;
#pragma unroll
    for (int g = 0; g < 16; g++) {
        float4 v = p4[g * 32 + lane];
        val[4*g+0] = v.x; val[4*g+1] = v.y; val[4*g+2] = v.z; val[4*g+3] = v.w;
        vmax = fmaxf(vmax, fmaxf(fmaxf(v.x, v.y), fmaxf(v.z, v.w)));
    }

    unsigned lo = __reduce_min_sync(FULL, fmono(vmax));
    unsigned hi = __reduce_max_sync(FULL, fmono(vmax));
    float loF = key_decode(lo);

    // ---- coarse: shrink until <=128 candidates (rarely iterates) ----
    int c_lo;
    {
        int c = 0;
#pragma unroll
        for (int j = 0; j < 64; j++) c += (val[j] >= loF) ? 1 : 0;
        c_lo = __reduce_add_sync(FULL, c);
    }
#pragma unroll 1
    for (int it = 0; it < 32 && c_lo > 128 && lo < hi; ++it) {
        unsigned span = hi - lo;
        unsigned mid = lo + (span >> 1) + (span & 1u);
        float mf = key_decode(mid);
        int c = 0;
#pragma unroll
        for (int j = 0; j < 64; j++) c += (val[j] >= mf) ? 1 : 0;
        c = __reduce_add_sync(FULL, c);
        if (c >= TOPK) { lo = mid; loF = mf; c_lo = c; }
        else            hi = mid - 1;
    }

    // ---- build candidate mask, compress via ffs loop ----
    unsigned long long candmask = 0ull;
#pragma unroll
    for (int j = 0; j < 64; j++)
        if (val[j] >= loF) candmask |= 1ull << j;
    int cnt = __popcll(candmask);
    int off = cnt;
#pragma unroll
    for (int d = 1; d < 32; d <<= 1) {
        int n = __shfl_up_sync(FULL, off, d);
        if (lane >= d) off += n;
    }
    int ncand = __shfl_sync(FULL, off, 31);
    off -= cnt;
    {
        unsigned long long m = candmask;
        int o = off;
        while (m) {
            int j = __ffsll(m) - 1;
            m &= m - 1;
            if (o < 128) s_cv[warp][o] = val[j];
            o++;
        }
    }
    if (ncand > 128) ncand = 128;
    __syncwarp();

    float cv[4];
#pragma unroll
    for (int r = 0; r < 4; r++) {
        int pos = lane + r * 32;
        cv[r] = (pos < ncand) ? s_cv[warp][pos] : -3.0e38f;
    }

    // ---- fine bisection over candidate regs (ballot counting) ----
#pragma unroll 1
    for (int it = 0; it < 32; ++it) {
        if (lo >= hi) break;
        unsigned span = hi - lo;
        unsigned mid = lo + (span >> 1) + (span & 1u);
        float mf = key_decode(mid);
        int c = 0;
#pragma unroll
        for (int r = 0; r < 4; r++)
            c += __popc(__ballot_sync(FULL, cv[r] >= mf));
        if (c >= TOPK) lo = mid; else hi = mid - 1;
    }
    float Tf = key_decode(lo);

    int cg = 0;
#pragma unroll
    for (int r = 0; r < 4; r++)
        cg += __popc(__ballot_sync(FULL, cv[r] > Tf));
    int rem = TOPK - cg;

    // ---- selection mask (one full pass), ties via ffs loop ----
    unsigned long long selmask = 0ull, tiemask = 0ull;
    float vin_l = 3.0e38f, vout_l = -3.0e38f;
#pragma unroll
    for (int j = 0; j < 64; j++) {
        float v = val[j];
        if (v > Tf)       { selmask |= 1ull << j; vin_l = fminf(vin_l, v); }
        else if (v == Tf) { tiemask |= 1ull << j; }
        else              { vout_l = fmaxf(vout_l, v); }
    }
    int tcnt = __popcll(tiemask);
    int toff = tcnt;
#pragma unroll
    for (int d = 1; d < 32; d <<= 1) {
        int n = __shfl_up_sync(FULL, toff, d);
        if (lane >= d) toff += n;
    }
    toff -= tcnt;
    {
        unsigned long long m = tiemask;
        int r = toff;
        while (m) {
            int j = __ffsll(m) - 1;
            m &= m - 1;
            if (r < rem) { selmask |= 1ull << j; vin_l = fminf(vin_l, val[j]); }
            else         { vout_l = fmaxf(vout_l, val[j]); }
            r++;
        }
    }

    unsigned vi = __reduce_min_sync(FULL, fmono(vin_l));
    unsigned vo = __reduce_max_sync(FULL, fmono(vout_l));
    float vin  = key_decode(vi);
    float vout = key_decode(vo);

    // ---- fp64 rescue of ambiguous boundary ----
    if (vin - vout < AMBIG_W) {
        float wlo = vout - AMBIG_W;
        float whi = vin + AMBIG_W;
        // mask pass + scan + ffs store (storage order irrelevant:
        // rescue ranks by (value desc, idx asc), not slot order)
        unsigned long long wmask = 0ull;
#pragma unroll
        for (int j = 0; j < 64; j++) {
            float v = val[j];
            if (v >= wlo && v <= whi) wmask |= 1ull << j;
        }
        int wcnt = __popcll(wmask);
        int woff = wcnt;
#pragma unroll
        for (int d = 1; d < 32; d <<= 1) {
            int n = __shfl_up_sync(FULL, woff, d);
            if (lane >= d) woff += n;
        }
        int ncw = __shfl_sync(FULL, woff, 31);
        woff -= wcnt;
        {
            unsigned long long m = wmask;
            int o = woff;
            while (m) {
                int j = __ffsll(m) - 1;
                m &= m - 1;
                if (o < MAXCAND) {
                    s_cidx[warp][o] = (j >> 2) * 128 + lane * 4 + (j & 3);
                    s_csel[warp][o] = (int)((selmask >> j) & 1ull);
                }
                o++;
            }
        }
        if (ncw > MAXCAND) ncw = MAXCAND;
        __syncwarp();

        const float* xr = x + (size_t)row * DIN;
        for (int c = 0; c < ncw; c++) {
            const float* wr = Wenc + (size_t)s_cidx[warp][c] * DIN;
            double s = 0.0;
#pragma unroll
            for (int t = 0; t < DIN / 32; t++) {
                int kk = lane + t * 32;
                s += (double)xr[kk] * (double)wr[kk];
            }
#pragma unroll
            for (int o2 = 16; o2 > 0; o2 >>= 1)
                s += __shfl_down_sync(FULL, s, o2);
            if (lane == 0) s_cval[warp][c] = s;
            __syncwarp();
        }

        if (lane == 0) {
            int nkeep = 0;
            for (int c = 0; c < ncw; c++) nkeep += s_csel[warp][c];
            unsigned chosen = 0;
            for (int s = 0; s < nkeep; s++) {
                int best = -1;
                for (int c = 0; c < ncw; c++) {
                    if (chosen & (1u << c)) continue;
                    if (best < 0 ||
                        s_cval[warp][c] > s_cval[warp][best] ||
                        (s_cval[warp][c] == s_cval[warp][best] &&
                         s_cidx[warp][c] < s_cidx[warp][best]))
                        best = c;
                }
                chosen |= (1u << best);
            }
            s_chosen[warp] = chosen;
        }
        __syncwarp();
        unsigned chosen = s_chosen[warp];

        for (int c = 0; c < ncw; c++) {
            int fi = s_cidx[warp][c];
            if (((fi >> 2) & 31) == lane) {
                int j = ((fi >> 7) << 2) | (fi & 3);
                if (chosen & (1u << c)) selmask |=  (1ull << j);
                else                    selmask &= ~(1ull << j);
            }
        }
        __syncwarp();
    }

    // ---- dense write (float4) ----
    float4* orow4 = (float4*)(hsp + (size_t)row * DHID);
#pragma unroll
    for (int g = 0; g < 16; g++) {
        float4 o;
        o.x = ((selmask >> (4*g+0)) & 1ull) ? fmaxf(val[4*g+0], 0.0f) : 0.0f;
        o.y = ((selmask >> (4*g+1)) & 1ull) ? fmaxf(val[4*g+1], 0.0f) : 0.0f;
        o.z = ((selmask >> (4*g+2)) & 1ull) ? fmaxf(val[4*g+2], 0.0f) : 0.0f;
        o.w = ((selmask >> (4*g+3)) & 1ull) ? fmaxf(val[4*g+3], 0.0f) : 0.0f;
        orow4[g * 32 + lane] = o;
    }

    // ---- compact list: scan + ffs loop ----
    int scnt = __popcll(selmask);
    int soff = scnt;
#pragma unroll
    for (int d = 1; d < 32; d <<= 1) {
        int n = __shfl_up_sync(FULL, soff, d);
        if (lane >= d) soff += n;
    }
    int nsel_tot = __shfl_sync(FULL, soff, 31);
    soff -= scnt;
    {
        unsigned long long m = selmask;
        int so = soff;
        while (m) {
            int j = __ffsll(m) - 1;
            m &= m - 1;
            if (so < TOPK) {
                g_tidx[(size_t)row * TOPK + so] = (j >> 2) * 128 + lane * 4 + (j & 3);
                g_tval[(size_t)row * TOPK + so] = fmaxf(val[j], 0.0f);
            }
            so++;
        }
    }
    if (nsel_tot < TOPK && lane == 0) {
        for (int s = nsel_tot; s < TOPK; s++) {
            g_tidx[(size_t)row * TOPK + s] = 0;
            g_tval[(size_t)row * TOPK + s] = 0.0f;
        }
    }
}

// ============================================================
// Sparse decoder: recon[row,:] = b_dec + sum_k val_k * Wt[idx_k,:]
// Wt in fp16 (math fp32).
// ============================================================
__global__ __launch_bounds__(192)
void decode_kernel(const float* __restrict__ bdec, float* __restrict__ recon)
{
    int row = blockIdx.x;
    int t = threadIdx.x;
    __shared__ float sval[TOPK];
    __shared__ int   sidx[TOPK];
    if (t < TOPK) {
        sval[t] = g_tval[(size_t)row * TOPK + t];
        sidx[t] = g_tidx[(size_t)row * TOPK + t];
    }
    __syncthreads();

    float4 acc = *(const float4*)&bdec[t * 4];
#pragma unroll 8
    for (int k = 0; k < TOPK; k++) {
        float v = sval[k];
        const __half* wr = g_Wt + (size_t)sidx[k] * DIN;
        uint2 u = ((const uint2*)wr)[t];
        __half2 h01 = *(__half2*)&u.x;
        __half2 h23 = *(__half2*)&u.y;
        float2 f01 = __half22float2(h01);
        float2 f23 = __half22float2(h23);
        acc.x += v * f01.x; acc.y += v * f01.y;
        acc.z += v * f23.x; acc.w += v * f23.y;
    }
    *(float4*)&recon[(size_t)row * DIN + t * 4] = acc;
}

// ============================================================
extern "C" void kernel_launch(void* const* d_in, const int* in_sizes, int n_in,
                              void* d_out, int out_size)
{
    const float* x     = (const float*)d_in[0];
    const float* W_enc = (const float*)d_in[1];
    const float* b_enc = (const float*)d_in[2];
    const float* W_dec = (const float*)d_in[3];
    const float* b_dec = (const float*)d_in[4];

    float* out   = (float*)d_out;
    float* recon = out;                                 // [B, 768]
    float* hsp   = out + (size_t)BATCH * DIN;           // [B, 2048]
    float* hpre  = hsp + (size_t)BATCH * DHID;          // [B, 2048]

    __half *ah, *bh;
    cudaGetSymbolAddress((void**)&ah, g_Ah);
    cudaGetSymbolAddress((void**)&bh, g_Bh);

    cudaFuncSetAttribute(gemm_fp16, cudaFuncAttributeMaxDynamicSharedMemorySize,
                         (int)GEMM_SMEM);

    round_x_kernel<<<(BATCH * DIN / 2) / 256, 256>>>(x, ah);
    round_x_kernel<<<(DHID * DIN / 2) / 256, 256>>>(W_enc, bh);
    transpose_kernel<<<dim3(DHID / 32, DIN / 32), dim3(32, 8)>>>(W_dec);
    gemm_fp16<<<dim3(DHID / 128, BATCH / 128), 256, GEMM_SMEM>>>(b_enc, hpre);
    topk_kernel<<<BATCH / 8, 256>>>(hpre, hsp, x, W_enc);
    decode_kernel<<<BATCH, 192>>>(b_dec, recon);
}